// round 15
// baseline (speedup 1.0000x reference)
#include <cuda_runtime.h>
#include <cuda_fp16.h>
#include <cstdint>

#define NN 100000
#define NE 1600000
#define D  128
#define NG 2048
#define NL 3
#define SCAN_NBLK ((NN + 1023) / 1024)   // 98
#define RS 132                            // smem row stride (halves), anti-conflict

// ---------------- scratch (device globals: alloc-free) ----------------
__device__ int      g_degi [NN];
__device__ float    g_dinv [NN];
__device__ int      g_fill [NN];
__device__ int      g_off  [NN + 1];
__device__ int      g_part [SCAN_NBLK];
__device__ __align__(16) int2 g_edge [NE];  // packed CSR: (src, norm bits)
__device__ int      g_start[NG + 1];
__device__ __align__(8) __half g_th [2][NN * D];  // t double-buffered (fp16)
__device__ float    g_agg  [NN * D];              // final-layer agg (fp32)
__device__ uint32_t g_wf   [NL * 16 * 16 * 64];

__device__ __forceinline__ void fma4(float4& a, float s, const float4& c) {
    a.x = fmaf(s, c.x, a.x);
    a.y = fmaf(s, c.y, a.y);
    a.z = fmaf(s, c.z, a.z);
    a.w = fmaf(s, c.w, a.w);
}

__device__ __forceinline__ float4 ldt4(const uint2* t2, long idx) {
    uint2 r = __ldg(&t2[idx]);
    __half2 h0 = *(__half2*)&r.x;
    __half2 h1 = *(__half2*)&r.y;
    float2 f0 = __half22float2(h0);
    float2 f1 = __half22float2(h1);
    return make_float4(f0.x, f0.y, f1.x, f1.y);
}

__device__ __forceinline__ uint32_t f2tf32(float f) {
    uint32_t r;
    asm("cvt.rna.tf32.f32 %0, %1;" : "=r"(r) : "f"(f));
    return r;
}

// warp-gathers one node's aggregated row into a float4 (lane j = feats 4j..4j+3)
__device__ __forceinline__ float4 gather_row(const uint2* t2, int d, int j) {
    float dv = g_dinv[d];
    float s2 = dv * dv;
    float4 acc = ldt4(t2, (long)d * 32 + j);
    acc.x *= s2; acc.y *= s2; acc.z *= s2; acc.w *= s2;
    int e   = g_off[d];
    int end = g_off[d + 1];
    for (; e + 2 <= end; e += 2) {
        int2 p0 = __ldcs(&g_edge[e]);
        int2 p1 = __ldcs(&g_edge[e + 1]);
        float4 v0 = ldt4(t2, (long)p0.x * 32 + j);
        float4 v1 = ldt4(t2, (long)p1.x * 32 + j);
        fma4(acc, __int_as_float(p0.y), v0);
        fma4(acc, __int_as_float(p1.y), v1);
    }
    if (e < end) {
        int2 p0 = __ldcs(&g_edge[e]);
        float4 v0 = ldt4(t2, (long)p0.x * 32 + j);
        fma4(acc, __int_as_float(p0.y), v0);
    }
    return acc;
}

// ---------------- init ------------------------------------------------
__global__ void k_init() {
    int i = blockIdx.x * blockDim.x + threadIdx.x;
    if (i < NN) { g_degi[i] = 1; g_fill[i] = 0; }
}

__global__ void k_deg(const int* __restrict__ ei) {
    int e = blockIdx.x * blockDim.x + threadIdx.x;
    if (e < NE) atomicAdd(&g_degi[__ldcs(&ei[NE + e])], 1);
}

// ---------------- 3-pass exclusive scan of (deg-1) ---------------------
__global__ void __launch_bounds__(1024)
k_scanA() {
    __shared__ int wsum[32];
    int tid = threadIdx.x, lane = tid & 31, w = tid >> 5;
    int i = blockIdx.x * 1024 + tid;
    int s = (i < NN) ? (g_degi[i] - 1) : 0;
    #pragma unroll
    for (int o = 16; o > 0; o >>= 1) s += __shfl_xor_sync(0xffffffffu, s, o);
    if (lane == 0) wsum[w] = s;
    __syncthreads();
    if (w == 0) {
        int t = wsum[lane];
        #pragma unroll
        for (int o = 16; o > 0; o >>= 1) t += __shfl_xor_sync(0xffffffffu, t, o);
        if (lane == 0) g_part[blockIdx.x] = t;
    }
}

__global__ void k_scanB() {
    int lane = threadIdx.x;
    int carry = 0;
    for (int base = 0; base < SCAN_NBLK; base += 32) {
        int i = base + lane;
        int v = (i < SCAN_NBLK) ? g_part[i] : 0;
        int incl = v;
        #pragma unroll
        for (int o = 1; o < 32; o <<= 1) {
            int t = __shfl_up_sync(0xffffffffu, incl, o);
            if (lane >= o) incl += t;
        }
        if (i < SCAN_NBLK) g_part[i] = carry + incl - v;
        carry += __shfl_sync(0xffffffffu, incl, 31);
    }
}

__global__ void __launch_bounds__(1024)
k_scanC() {
    __shared__ int wsum[32];
    int tid = threadIdx.x, lane = tid & 31, w = tid >> 5;
    int i = blockIdx.x * 1024 + tid;
    int val = (i < NN) ? (g_degi[i] - 1) : 0;
    int incl = val;
    #pragma unroll
    for (int o = 1; o < 32; o <<= 1) {
        int t = __shfl_up_sync(0xffffffffu, incl, o);
        if (lane >= o) incl += t;
    }
    if (lane == 31) wsum[w] = incl;
    __syncthreads();
    if (w == 0) {
        int s = wsum[lane];
        #pragma unroll
        for (int o = 1; o < 32; o <<= 1) {
            int t = __shfl_up_sync(0xffffffffu, s, o);
            if (lane >= o) s += t;
        }
        wsum[lane] = s;
    }
    __syncthreads();
    if (i < NN) {
        g_off[i] = g_part[blockIdx.x] + (w ? wsum[w - 1] : 0) + incl - val;
        g_dinv[i] = rsqrtf((float)g_degi[i]);
    }
    if (i == 0) g_off[NN] = NE;
}

// ---------------- CSR fill (packed) --------------------------------------
__global__ void k_fill(const int* __restrict__ ei) {
    int e = blockIdx.x * blockDim.x + threadIdx.x;
    if (e >= NE) return;
    int s = __ldcs(&ei[e]);
    int d = __ldcs(&ei[NE + e]);
    int pos = g_off[d] + atomicAdd(&g_fill[d], 1);
    float n = g_dinv[s] * g_dinv[d];
    g_edge[pos] = make_int2(s, __float_as_int(n));
}

// ---------------- graph boundaries --------------------------------------
__global__ void k_bnd(const int* __restrict__ batch) {
    int i = blockIdx.x * blockDim.x + threadIdx.x;
    if (i >= NN) return;
    int b1 = batch[i];
    int b0 = (i == 0) ? -1 : batch[i - 1];
    for (int g = b0 + 1; g <= b1; g++) g_start[g] = i;
    if (i == NN - 1)
        for (int g = b1 + 1; g <= NG; g++) g_start[g] = NN;
}

// ---------------- W -> tf32 fragment layout ------------------------------
__global__ void k_wprep(const float* __restrict__ W) {
    int tid = blockIdx.x * blockDim.x + threadIdx.x;
    if (tid >= NL * 16 * 16 * 32) return;
    int lane = tid & 31;
    int j    = (tid >> 5) & 15;
    int s    = (tid >> 9) & 15;
    int l    = tid >> 13;
    int g = lane >> 2, t = lane & 3;
    const float* Wl = W + l * D * D;
    float w0 = Wl[(8 * s + t) * D + 8 * j + g];
    float w1 = Wl[(8 * s + t + 4) * D + 8 * j + g];
    g_wf[tid * 2 + 0] = f2tf32(w0);
    g_wf[tid * 2 + 1] = f2tf32(w1);
}

// ---------------- layer-0 TF32 GEMM (A = x, fp32 global) ------------------
__global__ void __launch_bounds__(256)
k_gemm0(const float* __restrict__ x0) {
    int lane = threadIdx.x & 31;
    int w    = threadIdx.x >> 5;
    int g = lane >> 2, t = lane & 3;
    int m0 = blockIdx.x * 128 + w * 16;
    int row0 = m0 + g;
    int row1 = m0 + g + 8;
    int r0c = (row0 < NN) ? row0 : (NN - 1);
    int r1c = (row1 < NN) ? row1 : (NN - 1);

    float acc[16][4];
    #pragma unroll
    for (int j = 0; j < 16; j++)
        { acc[j][0] = 0.f; acc[j][1] = 0.f; acc[j][2] = 0.f; acc[j][3] = 0.f; }

    const uint32_t* wf = g_wf + lane * 2;   // layer 0

    #pragma unroll
    for (int s = 0; s < 16; s++) {
        int k0 = 8 * s;
        uint32_t a0 = f2tf32(__ldg(&x0[r0c * D + k0 + t]));
        uint32_t a1 = f2tf32(__ldg(&x0[r1c * D + k0 + t]));
        uint32_t a2 = f2tf32(__ldg(&x0[r0c * D + k0 + t + 4]));
        uint32_t a3 = f2tf32(__ldg(&x0[r1c * D + k0 + t + 4]));
        const uint32_t* wfs = wf + s * 16 * 64;
        #pragma unroll
        for (int j = 0; j < 16; j++) {
            uint2 bv = *(const uint2*)(wfs + j * 64);
            asm volatile(
                "mma.sync.aligned.m16n8k8.row.col.f32.tf32.tf32.f32 "
                "{%0,%1,%2,%3}, {%4,%5,%6,%7}, {%8,%9}, {%0,%1,%2,%3};"
                : "+f"(acc[j][0]), "+f"(acc[j][1]), "+f"(acc[j][2]), "+f"(acc[j][3])
                : "r"(a0), "r"(a1), "r"(a2), "r"(a3), "r"(bv.x), "r"(bv.y));
        }
    }

    __half2* th2 = (__half2*)g_th[0];
    #pragma unroll
    for (int j = 0; j < 16; j++) {
        int c = 8 * j + 2 * t;
        if (row0 < NN)
            th2[(row0 * D + c) >> 1] = __floats2half2_rn(acc[j][0], acc[j][1]);
        if (row1 < NN)
            th2[(row1 * D + c) >> 1] = __floats2half2_rn(acc[j][2], acc[j][3]);
    }
}

// ---------------- FUSED gather + GEMM for layers 1,2 ----------------------
// Phase 1: 8 warps gather 16 rows each (agg = Â·t_{l-1}), apply bias+relu,
//          store fp16 into smem (row stride RS halves, conflict-free).
// Phase 2: tf32 MMA with A-fragments from smem; writes t_l (other buffer).
__global__ void __launch_bounds__(256)
k_fused(const float* __restrict__ bias, int layer) {
    __shared__ __half sA[128 * RS];   // ~33 KB
    int lane = threadIdx.x & 31;
    int w    = threadIdx.x >> 5;
    int rowBase = blockIdx.x * 128;
    const uint2* t2 = (const uint2*)g_th[(layer + 1) & 1];  // read t_{l-1}

    float4 bb = __ldg(&((const float4*)bias)[lane]);        // feats 4*lane..+3

    for (int r = 0; r < 16; r++) {
        int lr = w * 16 + r;
        int d  = rowBase + lr;
        float4 acc = make_float4(0.f, 0.f, 0.f, 0.f);
        if (d < NN) {
            acc = gather_row(t2, d, lane);
            acc.x = fmaxf(acc.x + bb.x, 0.f);
            acc.y = fmaxf(acc.y + bb.y, 0.f);
            acc.z = fmaxf(acc.z + bb.z, 0.f);
            acc.w = fmaxf(acc.w + bb.w, 0.f);
        }
        __half2* s2 = (__half2*)&sA[lr * RS + lane * 4];
        s2[0] = __floats2half2_rn(acc.x, acc.y);
        s2[1] = __floats2half2_rn(acc.z, acc.w);
    }
    __syncthreads();

    int g = lane >> 2, t = lane & 3;
    int lr0 = w * 16 + g;
    int lr1 = lr0 + 8;
    int row0 = rowBase + lr0;
    int row1 = rowBase + lr1;

    float acc[16][4];
    #pragma unroll
    for (int j = 0; j < 16; j++)
        { acc[j][0] = 0.f; acc[j][1] = 0.f; acc[j][2] = 0.f; acc[j][3] = 0.f; }

    const uint32_t* wf = g_wf + (layer * 16) * 16 * 64 + lane * 2;

    #pragma unroll
    for (int s = 0; s < 16; s++) {
        int k0 = 8 * s;
        uint32_t a0 = f2tf32(__half2float(sA[lr0 * RS + k0 + t]));
        uint32_t a1 = f2tf32(__half2float(sA[lr1 * RS + k0 + t]));
        uint32_t a2 = f2tf32(__half2float(sA[lr0 * RS + k0 + t + 4]));
        uint32_t a3 = f2tf32(__half2float(sA[lr1 * RS + k0 + t + 4]));
        const uint32_t* wfs = wf + s * 16 * 64;
        #pragma unroll
        for (int j = 0; j < 16; j++) {
            uint2 bv = *(const uint2*)(wfs + j * 64);
            asm volatile(
                "mma.sync.aligned.m16n8k8.row.col.f32.tf32.tf32.f32 "
                "{%0,%1,%2,%3}, {%4,%5,%6,%7}, {%8,%9}, {%0,%1,%2,%3};"
                : "+f"(acc[j][0]), "+f"(acc[j][1]), "+f"(acc[j][2]), "+f"(acc[j][3])
                : "r"(a0), "r"(a1), "r"(a2), "r"(a3), "r"(bv.x), "r"(bv.y));
        }
    }

    __half2* th2 = (__half2*)g_th[layer & 1];               // write t_l
    #pragma unroll
    for (int j = 0; j < 16; j++) {
        int c = 8 * j + 2 * t;
        if (row0 < NN)
            th2[(row0 * D + c) >> 1] = __floats2half2_rn(acc[j][0], acc[j][1]);
        if (row1 < NN)
            th2[(row1 * D + c) >> 1] = __floats2half2_rn(acc[j][2], acc[j][3]);
    }
}

// ---------------- final gather (layer 2): t[0] -> agg (fp32) --------------
__global__ void __launch_bounds__(256)
k_gather2() {
    int gw = (blockIdx.x * blockDim.x + threadIdx.x) >> 5;
    if (gw >= NN) return;
    int j = threadIdx.x & 31;
    const uint2* t2 = (const uint2*)g_th[0];
    float4 acc = gather_row(t2, gw, j);
    __stcs(&((float4*)g_agg)[gw * 32 + j], acc);
}

// ---------------- fused pool + final linear ------------------------------
__global__ void __launch_bounds__(128)
k_poolout(const float* __restrict__ bias, const float* __restrict__ lin_w,
          const float* __restrict__ lin_b, float* __restrict__ out) {
    int g = blockIdx.x;
    int j = threadIdx.x;
    int beg = g_start[g];
    int end = g_start[g + 1];
    float bb = bias[j];
    float acc = 0.0f;
    for (int r = beg; r < end; r++)
        acc += fmaxf(__ldcs(&g_agg[r * D + j]) + bb, 0.0f);

    float p = acc * lin_w[j];
    #pragma unroll
    for (int o = 16; o > 0; o >>= 1) p += __shfl_xor_sync(0xffffffffu, p, o);

    __shared__ float ws[4];
    if ((j & 31) == 0) ws[j >> 5] = p;
    __syncthreads();
    if (j == 0) {
        float tot = ws[0] + ws[1] + ws[2] + ws[3];
        float cnt = (float)(end - beg);
        float inv = 1.0f / fmaxf(cnt, 1.0f);
        out[g] = tot * inv + lin_b[0];
    }
}

// ---------------- launch ----------------------------------------------------
extern "C" void kernel_launch(void* const* d_in, const int* in_sizes, int n_in,
                              void* d_out, int out_size) {
    const float *x = 0, *W = 0, *b = 0, *lin_w = 0, *lin_b = 0;
    const int   *ei = 0, *batch = 0;
    for (int i = 0; i < n_in; i++) {
        switch (in_sizes[i]) {
            case NN * D:      x     = (const float*)d_in[i]; break;
            case 2 * NE:      ei    = (const int*)d_in[i];   break;
            case NN:          batch = (const int*)d_in[i];   break;
            case NL * D * D:  W     = (const float*)d_in[i]; break;
            case NL * D:      b     = (const float*)d_in[i]; break;
            case D:           lin_w = (const float*)d_in[i]; break;
            case 1:           lin_b = (const float*)d_in[i]; break;
        }
    }
    float* out = (float*)d_out;

    static cudaStream_t side = 0;
    static cudaEvent_t evF = 0, evJ = 0, evB = 0;
    if (!side) {
        cudaStreamCreateWithFlags(&side, cudaStreamNonBlocking);
        cudaEventCreateWithFlags(&evF, cudaEventDisableTiming);
        cudaEventCreateWithFlags(&evJ, cudaEventDisableTiming);
        cudaEventCreateWithFlags(&evB, cudaEventDisableTiming);
    }

    const int T = 256;

    // fork: prep chain on side stream, concurrent with wprep + gemm0
    cudaEventRecord(evF, 0);
    cudaStreamWaitEvent(side, evF, 0);

    k_init <<<(NN + T - 1) / T, T, 0, side>>>();
    k_deg  <<<(NE + T - 1) / T, T, 0, side>>>(ei);
    k_scanA<<<SCAN_NBLK, 1024, 0, side>>>();
    k_scanB<<<1, 32, 0, side>>>();
    k_scanC<<<SCAN_NBLK, 1024, 0, side>>>();
    k_fill <<<(NE + T - 1) / T, T, 0, side>>>(ei);
    cudaEventRecord(evJ, side);               // CSR ready
    k_bnd  <<<(NN + T - 1) / T, T, 0, side>>>(batch);
    cudaEventRecord(evB, side);               // bnd ready

    int gemmGrid   = (NN + 127) / 128;        // 782
    int gatherGrid = (NN * 32 + T - 1) / T;

    k_wprep<<<(NL * 16 * 16 * 32 + T - 1) / T, T>>>(W);
    k_gemm0<<<gemmGrid, T>>>(x);              // writes t[0]

    // join: fused layers need CSR (side) + t[0] (main)
    cudaStreamWaitEvent(0, evJ, 0);

    k_fused<<<gemmGrid, T>>>(b + 0 * D, 1);   // reads t[0], writes t[1]
    k_fused<<<gemmGrid, T>>>(b + 1 * D, 2);   // reads t[1], writes t[0]
    k_gather2<<<gatherGrid, T>>>();           // reads t[0] -> agg

    cudaStreamWaitEvent(0, evB, 0);
    k_poolout<<<NG, 128>>>(b + 2 * D, lin_w, lin_b, out);
}

// round 16
// speedup vs baseline: 1.1872x; 1.1872x over previous
#include <cuda_runtime.h>
#include <cuda_fp16.h>
#include <cstdint>

#define NN 100000
#define NE 1600000
#define D  128
#define NG 2048
#define NL 3
#define SCAN_NBLK ((NN + 1023) / 1024)   // 98

// ---------------- scratch (device globals: alloc-free) ----------------
__device__ int      g_degi [NN];
__device__ float    g_dinv [NN];
__device__ int      g_fill [NN];
__device__ int      g_off  [NN + 1];
__device__ int      g_part [SCAN_NBLK];
__device__ __align__(8) int2 g_edge [NE];   // packed CSR: (src, norm bits)
__device__ int      g_start[NG + 1];
__device__ float    g_gsum [NG];
__device__ __align__(8) __half g_th [NN * D];   // t = h @ W, fp16
__device__ float    g_agg  [NN * D];            // aggregated, fp32
__device__ uint32_t g_wf   [NL * 16 * 16 * 64];

__device__ __forceinline__ void fma4(float4& a, float s, const float4& c) {
    a.x = fmaf(s, c.x, a.x);
    a.y = fmaf(s, c.y, a.y);
    a.z = fmaf(s, c.z, a.z);
    a.w = fmaf(s, c.w, a.w);
}

__device__ __forceinline__ float4 ldt4(const uint2* t2, long idx) {
    uint2 r = __ldg(&t2[idx]);
    __half2 h0 = *(__half2*)&r.x;
    __half2 h1 = *(__half2*)&r.y;
    float2 f0 = __half22float2(h0);
    float2 f1 = __half22float2(h1);
    return make_float4(f0.x, f0.y, f1.x, f1.y);
}

__device__ __forceinline__ uint32_t f2tf32(float f) {
    uint32_t r;
    asm("cvt.rna.tf32.f32 %0, %1;" : "=r"(r) : "f"(f));
    return r;
}

// warp-gathers one node's aggregated row (lane j owns feats 4j..4j+3)
__device__ __forceinline__ float4 gather_row(const uint2* t2, int d, int j) {
    float dv = g_dinv[d];
    float s2 = dv * dv;
    float4 acc = ldt4(t2, (long)d * 32 + j);
    acc.x *= s2; acc.y *= s2; acc.z *= s2; acc.w *= s2;
    int e   = g_off[d];
    int end = g_off[d + 1];
    for (; e + 2 <= end; e += 2) {
        int2 p0 = __ldcs(&g_edge[e]);
        int2 p1 = __ldcs(&g_edge[e + 1]);
        float4 v0 = ldt4(t2, (long)p0.x * 32 + j);
        float4 v1 = ldt4(t2, (long)p1.x * 32 + j);
        fma4(acc, __int_as_float(p0.y), v0);
        fma4(acc, __int_as_float(p1.y), v1);
    }
    if (e < end) {
        int2 p0 = __ldcs(&g_edge[e]);
        float4 v0 = ldt4(t2, (long)p0.x * 32 + j);
        fma4(acc, __int_as_float(p0.y), v0);
    }
    return acc;
}

// ---------------- init ------------------------------------------------
__global__ void k_init() {
    int i = blockIdx.x * blockDim.x + threadIdx.x;
    if (i < NN) { g_degi[i] = 1; g_fill[i] = 0; }
    if (i < NG) g_gsum[i] = 0.0f;
}

__global__ void k_deg(const int* __restrict__ ei) {
    int e = blockIdx.x * blockDim.x + threadIdx.x;
    if (e < NE) atomicAdd(&g_degi[__ldcs(&ei[NE + e])], 1);
}

// ---------------- 3-pass exclusive scan of (deg-1) ---------------------
__global__ void __launch_bounds__(1024)
k_scanA() {
    __shared__ int wsum[32];
    int tid = threadIdx.x, lane = tid & 31, w = tid >> 5;
    int i = blockIdx.x * 1024 + tid;
    int s = (i < NN) ? (g_degi[i] - 1) : 0;
    #pragma unroll
    for (int o = 16; o > 0; o >>= 1) s += __shfl_xor_sync(0xffffffffu, s, o);
    if (lane == 0) wsum[w] = s;
    __syncthreads();
    if (w == 0) {
        int t = wsum[lane];
        #pragma unroll
        for (int o = 16; o > 0; o >>= 1) t += __shfl_xor_sync(0xffffffffu, t, o);
        if (lane == 0) g_part[blockIdx.x] = t;
    }
}

__global__ void k_scanB() {
    int lane = threadIdx.x;
    int carry = 0;
    for (int base = 0; base < SCAN_NBLK; base += 32) {
        int i = base + lane;
        int v = (i < SCAN_NBLK) ? g_part[i] : 0;
        int incl = v;
        #pragma unroll
        for (int o = 1; o < 32; o <<= 1) {
            int t = __shfl_up_sync(0xffffffffu, incl, o);
            if (lane >= o) incl += t;
        }
        if (i < SCAN_NBLK) g_part[i] = carry + incl - v;
        carry += __shfl_sync(0xffffffffu, incl, 31);
    }
}

__global__ void __launch_bounds__(1024)
k_scanC() {
    __shared__ int wsum[32];
    int tid = threadIdx.x, lane = tid & 31, w = tid >> 5;
    int i = blockIdx.x * 1024 + tid;
    int val = (i < NN) ? (g_degi[i] - 1) : 0;
    int incl = val;
    #pragma unroll
    for (int o = 1; o < 32; o <<= 1) {
        int t = __shfl_up_sync(0xffffffffu, incl, o);
        if (lane >= o) incl += t;
    }
    if (lane == 31) wsum[w] = incl;
    __syncthreads();
    if (w == 0) {
        int s = wsum[lane];
        #pragma unroll
        for (int o = 1; o < 32; o <<= 1) {
            int t = __shfl_up_sync(0xffffffffu, s, o);
            if (lane >= o) s += t;
        }
        wsum[lane] = s;
    }
    __syncthreads();
    if (i < NN) {
        g_off[i] = g_part[blockIdx.x] + (w ? wsum[w - 1] : 0) + incl - val;
        g_dinv[i] = rsqrtf((float)g_degi[i]);
    }
    if (i == 0) g_off[NN] = NE;
}

// ---------------- CSR fill (packed) --------------------------------------
__global__ void k_fill(const int* __restrict__ ei) {
    int e = blockIdx.x * blockDim.x + threadIdx.x;
    if (e >= NE) return;
    int s = __ldcs(&ei[e]);
    int d = __ldcs(&ei[NE + e]);
    int pos = g_off[d] + atomicAdd(&g_fill[d], 1);
    float n = g_dinv[s] * g_dinv[d];
    g_edge[pos] = make_int2(s, __float_as_int(n));
}

// ---------------- graph boundaries --------------------------------------
__global__ void k_bnd(const int* __restrict__ batch) {
    int i = blockIdx.x * blockDim.x + threadIdx.x;
    if (i >= NN) return;
    int b1 = batch[i];
    int b0 = (i == 0) ? -1 : batch[i - 1];
    for (int g = b0 + 1; g <= b1; g++) g_start[g] = i;
    if (i == NN - 1)
        for (int g = b1 + 1; g <= NG; g++) g_start[g] = NN;
}

// ---------------- W -> tf32 fragment layout ------------------------------
__global__ void k_wprep(const float* __restrict__ W) {
    int tid = blockIdx.x * blockDim.x + threadIdx.x;
    if (tid >= NL * 16 * 16 * 32) return;
    int lane = tid & 31;
    int j    = (tid >> 5) & 15;
    int s    = (tid >> 9) & 15;
    int l    = tid >> 13;
    int g = lane >> 2, t = lane & 3;
    const float* Wl = W + l * D * D;
    float w0 = Wl[(8 * s + t) * D + 8 * j + g];
    float w1 = Wl[(8 * s + t + 4) * D + 8 * j + g];
    g_wf[tid * 2 + 0] = f2tf32(w0);
    g_wf[tid * 2 + 1] = f2tf32(w1);
}

// ---------------- TF32 tensor-core GEMM ----------------------------------
__global__ void __launch_bounds__(256)
k_gemm(const float* __restrict__ x0, const float* __restrict__ bias, int layer) {
    const float* in = (layer == 0) ? x0 : g_agg;
    int lane = threadIdx.x & 31;
    int w    = threadIdx.x >> 5;
    int g = lane >> 2, t = lane & 3;
    int m0 = blockIdx.x * 128 + w * 16;
    int row0 = m0 + g;
    int row1 = m0 + g + 8;
    int r0c = (row0 < NN) ? row0 : (NN - 1);
    int r1c = (row1 < NN) ? row1 : (NN - 1);

    float acc[16][4];
    #pragma unroll
    for (int j = 0; j < 16; j++)
        { acc[j][0] = 0.f; acc[j][1] = 0.f; acc[j][2] = 0.f; acc[j][3] = 0.f; }

    const uint32_t* wf = g_wf + (layer * 16) * 16 * 64 + lane * 2;

    #pragma unroll
    for (int s = 0; s < 16; s++) {
        int k0 = 8 * s;
        float a0f = __ldg(&in[r0c * D + k0 + t]);
        float a1f = __ldg(&in[r1c * D + k0 + t]);
        float a2f = __ldg(&in[r0c * D + k0 + t + 4]);
        float a3f = __ldg(&in[r1c * D + k0 + t + 4]);
        if (layer != 0) {
            float b0 = __ldg(&bias[k0 + t]);
            float b1 = __ldg(&bias[k0 + t + 4]);
            a0f = fmaxf(a0f + b0, 0.f);
            a1f = fmaxf(a1f + b0, 0.f);
            a2f = fmaxf(a2f + b1, 0.f);
            a3f = fmaxf(a3f + b1, 0.f);
        }
        uint32_t a0 = f2tf32(a0f), a1 = f2tf32(a1f);
        uint32_t a2 = f2tf32(a2f), a3 = f2tf32(a3f);

        const uint32_t* wfs = wf + s * 16 * 64;
        #pragma unroll
        for (int j = 0; j < 16; j++) {
            uint2 bv = *(const uint2*)(wfs + j * 64);
            asm volatile(
                "mma.sync.aligned.m16n8k8.row.col.f32.tf32.tf32.f32 "
                "{%0,%1,%2,%3}, {%4,%5,%6,%7}, {%8,%9}, {%0,%1,%2,%3};"
                : "+f"(acc[j][0]), "+f"(acc[j][1]), "+f"(acc[j][2]), "+f"(acc[j][3])
                : "r"(a0), "r"(a1), "r"(a2), "r"(a3), "r"(bv.x), "r"(bv.y));
        }
    }

    __half2* th2 = (__half2*)g_th;
    #pragma unroll
    for (int j = 0; j < 16; j++) {
        int c = 8 * j + 2 * t;
        if (row0 < NN)
            th2[(row0 * D + c) >> 1] = __floats2half2_rn(acc[j][0], acc[j][1]);
        if (row1 < NN)
            th2[(row1 * D + c) >> 1] = __floats2half2_rn(acc[j][2], acc[j][3]);
    }
}

// ---------------- gather (layers 0,1): agg[d] = Â·t ----------------------
__global__ void __launch_bounds__(256)
k_gather() {
    int gw = (blockIdx.x * blockDim.x + threadIdx.x) >> 5;
    if (gw >= NN) return;
    int j = threadIdx.x & 31;
    const uint2* t2 = (const uint2*)g_th;
    float4 acc = gather_row(t2, gw, j);
    __stcs(&((float4*)g_agg)[gw * 32 + j], acc);
}

// ---------------- final gather fused with pool ----------------------------
// Warp per node: row = Â·t, p = relu(row + b2) . lin_w, atomicAdd to graph.
__global__ void __launch_bounds__(256)
k_gpool(const int* __restrict__ batch, const float* __restrict__ bias,
        const float* __restrict__ lin_w) {
    int gw = (blockIdx.x * blockDim.x + threadIdx.x) >> 5;
    if (gw >= NN) return;
    int j = threadIdx.x & 31;
    const uint2* t2 = (const uint2*)g_th;
    float4 acc = gather_row(t2, gw, j);

    float4 bb = __ldg(&((const float4*)bias)[j]);
    float4 lw = __ldg(&((const float4*)lin_w)[j]);
    float p = fmaxf(acc.x + bb.x, 0.f) * lw.x
            + fmaxf(acc.y + bb.y, 0.f) * lw.y
            + fmaxf(acc.z + bb.z, 0.f) * lw.z
            + fmaxf(acc.w + bb.w, 0.f) * lw.w;
    #pragma unroll
    for (int o = 16; o > 0; o >>= 1) p += __shfl_xor_sync(0xffffffffu, p, o);
    if (j == 0) atomicAdd(&g_gsum[batch[gw]], p);
}

// ---------------- finalize: out[g] = gsum/cnt + lin_b ---------------------
__global__ void k_fin(const float* __restrict__ lin_b, float* __restrict__ out) {
    int g = blockIdx.x * blockDim.x + threadIdx.x;
    if (g >= NG) return;
    float cnt = (float)(g_start[g + 1] - g_start[g]);
    out[g] = g_gsum[g] / fmaxf(cnt, 1.0f) + lin_b[0];
}

// ---------------- launch ----------------------------------------------------
extern "C" void kernel_launch(void* const* d_in, const int* in_sizes, int n_in,
                              void* d_out, int out_size) {
    const float *x = 0, *W = 0, *b = 0, *lin_w = 0, *lin_b = 0;
    const int   *ei = 0, *batch = 0;
    for (int i = 0; i < n_in; i++) {
        switch (in_sizes[i]) {
            case NN * D:      x     = (const float*)d_in[i]; break;
            case 2 * NE:      ei    = (const int*)d_in[i];   break;
            case NN:          batch = (const int*)d_in[i];   break;
            case NL * D * D:  W     = (const float*)d_in[i]; break;
            case NL * D:      b     = (const float*)d_in[i]; break;
            case D:           lin_w = (const float*)d_in[i]; break;
            case 1:           lin_b = (const float*)d_in[i]; break;
        }
    }
    float* out = (float*)d_out;

    static cudaStream_t side = 0;
    static cudaEvent_t evF = 0, evJ = 0, evB = 0;
    if (!side) {
        cudaStreamCreateWithFlags(&side, cudaStreamNonBlocking);
        cudaEventCreateWithFlags(&evF, cudaEventDisableTiming);
        cudaEventCreateWithFlags(&evJ, cudaEventDisableTiming);
        cudaEventCreateWithFlags(&evB, cudaEventDisableTiming);
    }

    const int T = 256;

    // fork: prep chain on side stream, concurrent with wprep + gemm0
    cudaEventRecord(evF, 0);
    cudaStreamWaitEvent(side, evF, 0);

    k_init <<<(NN + T - 1) / T, T, 0, side>>>();
    k_deg  <<<(NE + T - 1) / T, T, 0, side>>>(ei);
    k_scanA<<<SCAN_NBLK, 1024, 0, side>>>();
    k_scanB<<<1, 32, 0, side>>>();
    k_scanC<<<SCAN_NBLK, 1024, 0, side>>>();
    k_fill <<<(NE + T - 1) / T, T, 0, side>>>(ei);
    cudaEventRecord(evJ, side);               // CSR ready (bnd off join path)
    k_bnd  <<<(NN + T - 1) / T, T, 0, side>>>(batch);
    cudaEventRecord(evB, side);               // bnd ready

    int gemmGrid   = (NN + 127) / 128;
    int gatherGrid = (NN * 32 + T - 1) / T;

    k_wprep<<<(NL * 16 * 16 * 32 + T - 1) / T, T>>>(W);
    k_gemm <<<gemmGrid, T>>>(x, b, 0);

    // join: gather0 needs fill (side) + gemm0 (main)
    cudaStreamWaitEvent(0, evJ, 0);

    k_gather<<<gatherGrid, T>>>();
    k_gemm  <<<gemmGrid, T>>>(x, b + 0 * D, 1);
    k_gather<<<gatherGrid, T>>>();
    k_gemm  <<<gemmGrid, T>>>(x, b + 1 * D, 2);
    k_gpool <<<gatherGrid, T>>>(batch, b + 2 * D, lin_w);

    cudaStreamWaitEvent(0, evB, 0);
    k_fin<<<(NG + T - 1) / T, T>>>(lin_b, out);
}

// round 17
// speedup vs baseline: 1.2046x; 1.0147x over previous
#include <cuda_runtime.h>
#include <cuda_fp16.h>
#include <cstdint>

#define NN 100000
#define NE 1600000
#define D  128
#define NG 2048
#define NL 3
#define SCAN_NBLK ((NN + 1023) / 1024)   // 98

// ---------------- scratch (device globals: alloc-free) ----------------
__device__ int      g_degi [NN];
__device__ float    g_dinv [NN];
__device__ int      g_fill [NN];
__device__ int      g_off  [NN + 1];
__device__ int      g_part [SCAN_NBLK];
__device__ __align__(8) int2 g_edge [NE];   // packed CSR: (src, norm bits)
__device__ int      g_start[NG + 1];
__device__ float    g_gsum [NG];
__device__ __align__(8) __half g_th [NN * D];   // t = h @ W, fp16
__device__ float    g_agg  [NN * D];            // aggregated, fp32
__device__ uint32_t g_wf   [NL * 16 * 16 * 64];

__device__ __forceinline__ void fma4(float4& a, float s, const float4& c) {
    a.x = fmaf(s, c.x, a.x);
    a.y = fmaf(s, c.y, a.y);
    a.z = fmaf(s, c.z, a.z);
    a.w = fmaf(s, c.w, a.w);
}

// load 4 halves (8B) via L2-only path (t rows have ~0% L1 hit rate)
__device__ __forceinline__ float4 ldt4(const uint2* t2, long idx) {
    uint2 r = __ldcg(&t2[idx]);
    __half2 h0 = *(__half2*)&r.x;
    __half2 h1 = *(__half2*)&r.y;
    float2 f0 = __half22float2(h0);
    float2 f1 = __half22float2(h1);
    return make_float4(f0.x, f0.y, f1.x, f1.y);
}

__device__ __forceinline__ uint32_t f2tf32(float f) {
    uint32_t r;
    asm("cvt.rna.tf32.f32 %0, %1;" : "=r"(r) : "f"(f));
    return r;
}

// warp-gathers one node's aggregated row (lane j owns feats 4j..4j+3)
__device__ __forceinline__ float4 gather_row(const uint2* t2, int d, int j) {
    float dv = g_dinv[d];
    float s2 = dv * dv;
    float4 acc = ldt4(t2, (long)d * 32 + j);
    acc.x *= s2; acc.y *= s2; acc.z *= s2; acc.w *= s2;
    int e   = g_off[d];
    int end = g_off[d + 1];
    for (; e + 2 <= end; e += 2) {
        int2 p0 = __ldcs(&g_edge[e]);
        int2 p1 = __ldcs(&g_edge[e + 1]);
        float4 v0 = ldt4(t2, (long)p0.x * 32 + j);
        float4 v1 = ldt4(t2, (long)p1.x * 32 + j);
        fma4(acc, __int_as_float(p0.y), v0);
        fma4(acc, __int_as_float(p1.y), v1);
    }
    if (e < end) {
        int2 p0 = __ldcs(&g_edge[e]);
        float4 v0 = ldt4(t2, (long)p0.x * 32 + j);
        fma4(acc, __int_as_float(p0.y), v0);
    }
    return acc;
}

// ---------------- init + graph boundaries (merged) -----------------------
__global__ void k_init(const int* __restrict__ batch) {
    int i = blockIdx.x * blockDim.x + threadIdx.x;
    if (i < NG) g_gsum[i] = 0.0f;
    if (i >= NN) return;
    g_degi[i] = 1;           // self loop
    g_fill[i] = 0;
    int b1 = batch[i];
    int b0 = (i == 0) ? -1 : batch[i - 1];
    for (int g = b0 + 1; g <= b1; g++) g_start[g] = i;
    if (i == NN - 1)
        for (int g = b1 + 1; g <= NG; g++) g_start[g] = NN;
}

__global__ void k_deg(const int* __restrict__ ei) {
    int e = blockIdx.x * blockDim.x + threadIdx.x;
    if (e < NE) atomicAdd(&g_degi[__ldcs(&ei[NE + e])], 1);
}

// ---------------- scan pass A: per-block sums -----------------------------
__global__ void __launch_bounds__(1024)
k_scanA() {
    __shared__ int wsum[32];
    int tid = threadIdx.x, lane = tid & 31, w = tid >> 5;
    int i = blockIdx.x * 1024 + tid;
    int s = (i < NN) ? (g_degi[i] - 1) : 0;
    #pragma unroll
    for (int o = 16; o > 0; o >>= 1) s += __shfl_xor_sync(0xffffffffu, s, o);
    if (lane == 0) wsum[w] = s;
    __syncthreads();
    if (w == 0) {
        int t = wsum[lane];
        #pragma unroll
        for (int o = 16; o > 0; o >>= 1) t += __shfl_xor_sync(0xffffffffu, t, o);
        if (lane == 0) g_part[blockIdx.x] = t;
    }
}

// ---------------- scan pass C: redundant partial-scan per block ----------
// Each block scans the 98 raw partials itself (no separate pass-B kernel).
__global__ void __launch_bounds__(1024)
k_scanC() {
    __shared__ int wsum[32];
    __shared__ int sBase;
    int tid = threadIdx.x, lane = tid & 31, w = tid >> 5;

    if (w == 0) {            // warp 0: exclusive-scan g_part locally
        int carry = 0, myBase = 0;
        for (int base = 0; base < SCAN_NBLK; base += 32) {
            int idx = base + lane;
            int v = (idx < SCAN_NBLK) ? g_part[idx] : 0;
            int incl = v;
            #pragma unroll
            for (int o = 1; o < 32; o <<= 1) {
                int t = __shfl_up_sync(0xffffffffu, incl, o);
                if (lane >= o) incl += t;
            }
            if (idx == (int)blockIdx.x) myBase = carry + incl - v;
            carry += __shfl_sync(0xffffffffu, incl, 31);
        }
        // lane holding blockIdx.x publishes the base
        int srcLane = blockIdx.x & 31;
        int chunk   = blockIdx.x >> 5;
        // myBase is only valid on the lane where idx matched; reduce via max
        #pragma unroll
        for (int o = 16; o > 0; o >>= 1)
            myBase = max(myBase, __shfl_xor_sync(0xffffffffu, myBase, o));
        (void)srcLane; (void)chunk;
        if (lane == 0) sBase = myBase;
    }
    __syncthreads();

    int i = blockIdx.x * 1024 + tid;
    int val = (i < NN) ? (g_degi[i] - 1) : 0;
    int incl = val;
    #pragma unroll
    for (int o = 1; o < 32; o <<= 1) {
        int t = __shfl_up_sync(0xffffffffu, incl, o);
        if (lane >= o) incl += t;
    }
    if (lane == 31) wsum[w] = incl;
    __syncthreads();
    if (w == 0) {
        int s = wsum[lane];
        #pragma unroll
        for (int o = 1; o < 32; o <<= 1) {
            int t = __shfl_up_sync(0xffffffffu, s, o);
            if (lane >= o) s += t;
        }
        wsum[lane] = s;
    }
    __syncthreads();
    if (i < NN) {
        g_off[i] = sBase + (w ? wsum[w - 1] : 0) + incl - val;
        g_dinv[i] = rsqrtf((float)g_degi[i]);
    }
    if (i == 0) g_off[NN] = NE;
}

// ---------------- CSR fill (packed) --------------------------------------
__global__ void k_fill(const int* __restrict__ ei) {
    int e = blockIdx.x * blockDim.x + threadIdx.x;
    if (e >= NE) return;
    int s = __ldcs(&ei[e]);
    int d = __ldcs(&ei[NE + e]);
    int pos = g_off[d] + atomicAdd(&g_fill[d], 1);
    float n = g_dinv[s] * g_dinv[d];
    g_edge[pos] = make_int2(s, __float_as_int(n));
}

// ---------------- W -> tf32 fragment layout ------------------------------
__global__ void k_wprep(const float* __restrict__ W) {
    int tid = blockIdx.x * blockDim.x + threadIdx.x;
    if (tid >= NL * 16 * 16 * 32) return;
    int lane = tid & 31;
    int j    = (tid >> 5) & 15;
    int s    = (tid >> 9) & 15;
    int l    = tid >> 13;
    int g = lane >> 2, t = lane & 3;
    const float* Wl = W + l * D * D;
    float w0 = Wl[(8 * s + t) * D + 8 * j + g];
    float w1 = Wl[(8 * s + t + 4) * D + 8 * j + g];
    g_wf[tid * 2 + 0] = f2tf32(w0);
    g_wf[tid * 2 + 1] = f2tf32(w1);
}

// ---------------- TF32 tensor-core GEMM ----------------------------------
__global__ void __launch_bounds__(256)
k_gemm(const float* __restrict__ x0, const float* __restrict__ bias, int layer) {
    const float* in = (layer == 0) ? x0 : g_agg;
    int lane = threadIdx.x & 31;
    int w    = threadIdx.x >> 5;
    int g = lane >> 2, t = lane & 3;
    int m0 = blockIdx.x * 128 + w * 16;
    int row0 = m0 + g;
    int row1 = m0 + g + 8;
    int r0c = (row0 < NN) ? row0 : (NN - 1);
    int r1c = (row1 < NN) ? row1 : (NN - 1);

    float acc[16][4];
    #pragma unroll
    for (int j = 0; j < 16; j++)
        { acc[j][0] = 0.f; acc[j][1] = 0.f; acc[j][2] = 0.f; acc[j][3] = 0.f; }

    const uint32_t* wf = g_wf + (layer * 16) * 16 * 64 + lane * 2;

    #pragma unroll
    for (int s = 0; s < 16; s++) {
        int k0 = 8 * s;
        float a0f = __ldg(&in[r0c * D + k0 + t]);
        float a1f = __ldg(&in[r1c * D + k0 + t]);
        float a2f = __ldg(&in[r0c * D + k0 + t + 4]);
        float a3f = __ldg(&in[r1c * D + k0 + t + 4]);
        if (layer != 0) {
            float b0 = __ldg(&bias[k0 + t]);
            float b1 = __ldg(&bias[k0 + t + 4]);
            a0f = fmaxf(a0f + b0, 0.f);
            a1f = fmaxf(a1f + b0, 0.f);
            a2f = fmaxf(a2f + b1, 0.f);
            a3f = fmaxf(a3f + b1, 0.f);
        }
        uint32_t a0 = f2tf32(a0f), a1 = f2tf32(a1f);
        uint32_t a2 = f2tf32(a2f), a3 = f2tf32(a3f);

        const uint32_t* wfs = wf + s * 16 * 64;
        #pragma unroll
        for (int j = 0; j < 16; j++) {
            uint2 bv = *(const uint2*)(wfs + j * 64);
            asm volatile(
                "mma.sync.aligned.m16n8k8.row.col.f32.tf32.tf32.f32 "
                "{%0,%1,%2,%3}, {%4,%5,%6,%7}, {%8,%9}, {%0,%1,%2,%3};"
                : "+f"(acc[j][0]), "+f"(acc[j][1]), "+f"(acc[j][2]), "+f"(acc[j][3])
                : "r"(a0), "r"(a1), "r"(a2), "r"(a3), "r"(bv.x), "r"(bv.y));
        }
    }

    __half2* th2 = (__half2*)g_th;
    #pragma unroll
    for (int j = 0; j < 16; j++) {
        int c = 8 * j + 2 * t;
        if (row0 < NN)
            th2[(row0 * D + c) >> 1] = __floats2half2_rn(acc[j][0], acc[j][1]);
        if (row1 < NN)
            th2[(row1 * D + c) >> 1] = __floats2half2_rn(acc[j][2], acc[j][3]);
    }
}

// ---------------- gather (layers 0,1): agg[d] = Â·t ----------------------
__global__ void __launch_bounds__(256)
k_gather() {
    int gw = (blockIdx.x * blockDim.x + threadIdx.x) >> 5;
    if (gw >= NN) return;
    int j = threadIdx.x & 31;
    const uint2* t2 = (const uint2*)g_th;
    float4 acc = gather_row(t2, gw, j);
    __stcs(&((float4*)g_agg)[gw * 32 + j], acc);
}

// ---------------- final gather fused with pool ----------------------------
__global__ void __launch_bounds__(256)
k_gpool(const int* __restrict__ batch, const float* __restrict__ bias,
        const float* __restrict__ lin_w) {
    int gw = (blockIdx.x * blockDim.x + threadIdx.x) >> 5;
    if (gw >= NN) return;
    int j = threadIdx.x & 31;
    const uint2* t2 = (const uint2*)g_th;
    float4 acc = gather_row(t2, gw, j);

    float4 bb = __ldg(&((const float4*)bias)[j]);
    float4 lw = __ldg(&((const float4*)lin_w)[j]);
    float p = fmaxf(acc.x + bb.x, 0.f) * lw.x
            + fmaxf(acc.y + bb.y, 0.f) * lw.y
            + fmaxf(acc.z + bb.z, 0.f) * lw.z
            + fmaxf(acc.w + bb.w, 0.f) * lw.w;
    #pragma unroll
    for (int o = 16; o > 0; o >>= 1) p += __shfl_xor_sync(0xffffffffu, p, o);
    if (j == 0) atomicAdd(&g_gsum[batch[gw]], p);
}

// ---------------- finalize: out[g] = gsum/cnt + lin_b ---------------------
__global__ void k_fin(const float* __restrict__ lin_b, float* __restrict__ out) {
    int g = blockIdx.x * blockDim.x + threadIdx.x;
    if (g >= NG) return;
    float cnt = (float)(g_start[g + 1] - g_start[g]);
    out[g] = g_gsum[g] / fmaxf(cnt, 1.0f) + lin_b[0];
}

// ---------------- launch ----------------------------------------------------
extern "C" void kernel_launch(void* const* d_in, const int* in_sizes, int n_in,
                              void* d_out, int out_size) {
    const float *x = 0, *W = 0, *b = 0, *lin_w = 0, *lin_b = 0;
    const int   *ei = 0, *batch = 0;
    for (int i = 0; i < n_in; i++) {
        switch (in_sizes[i]) {
            case NN * D:      x     = (const float*)d_in[i]; break;
            case 2 * NE:      ei    = (const int*)d_in[i];   break;
            case NN:          batch = (const int*)d_in[i];   break;
            case NL * D * D:  W     = (const float*)d_in[i]; break;
            case NL * D:      b     = (const float*)d_in[i]; break;
            case D:           lin_w = (const float*)d_in[i]; break;
            case 1:           lin_b = (const float*)d_in[i]; break;
        }
    }
    float* out = (float*)d_out;

    static cudaStream_t side = 0;
    static cudaEvent_t evF = 0, evJ = 0;
    if (!side) {
        cudaStreamCreateWithFlags(&side, cudaStreamNonBlocking);
        cudaEventCreateWithFlags(&evF, cudaEventDisableTiming);
        cudaEventCreateWithFlags(&evJ, cudaEventDisableTiming);
    }

    const int T = 256;

    // fork: prep chain on side stream, concurrent with wprep + gemm0
    cudaEventRecord(evF, 0);
    cudaStreamWaitEvent(side, evF, 0);

    k_init <<<(NN + T - 1) / T, T, 0, side>>>(batch);   // init + bnd merged
    k_deg  <<<(NE + T - 1) / T, T, 0, side>>>(ei);
    k_scanA<<<SCAN_NBLK, 1024, 0, side>>>();
    k_scanC<<<SCAN_NBLK, 1024, 0, side>>>();            // self-scans partials
    k_fill <<<(NE + T - 1) / T, T, 0, side>>>(ei);
    cudaEventRecord(evJ, side);                          // CSR (+bnd) ready

    int gemmGrid   = (NN + 127) / 128;
    int gatherGrid = (NN * 32 + T - 1) / T;

    k_wprep<<<(NL * 16 * 16 * 32 + T - 1) / T, T>>>(W);
    k_gemm <<<gemmGrid, T>>>(x, b, 0);

    // join: gather0 needs fill (side) + gemm0 (main)
    cudaStreamWaitEvent(0, evJ, 0);

    k_gather<<<gatherGrid, T>>>();
    k_gemm  <<<gemmGrid, T>>>(x, b + 0 * D, 1);
    k_gather<<<gatherGrid, T>>>();
    k_gemm  <<<gemmGrid, T>>>(x, b + 1 * D, 2);
    k_gpool <<<gatherGrid, T>>>(batch, b + 2 * D, lin_w);

    k_fin<<<(NG + T - 1) / T, T>>>(lin_b, out);   // ordered behind evJ on main
}